// round 4
// baseline (speedup 1.0000x reference)
#include <cuda_runtime.h>
#include <cuda_fp16.h>
#include <math.h>
#include <stdint.h>

#define NENT 150000
#define NRELN 500
#define HD 128
#define DEG 32
#define TOPK 10

// -------- scratch (device globals; no allocation allowed) --------
__device__ float g_hnode[150016 * 128];
__device__ float g_neigh[150016 * 128];
__device__ float g_hrel[512 * 128];
__device__ uint32_t g_hrelh[512 * 64];     // h_rel as half2 pairs
__device__ float g_ssrc[150016];
__device__ float g_sdst[150016];
__device__ float g_srel[512];
// pre-transposed + swizzled fp16-split weight images: [matrix][hi 32KB | lo 32KB]
__device__ __align__(16) unsigned char g_Bimg[3][65536];

// ================= helpers =================
__device__ __forceinline__ uint32_t smem_u32(const void* p) {
    uint32_t a;
    asm("{ .reg .u64 t; cvta.to.shared.u64 t, %1; cvt.u32.u64 %0, t; }" : "=r"(a) : "l"(p));
    return a;
}
__device__ __forceinline__ void ldsm_x4(uint32_t* r, uint32_t addr) {
    asm volatile("ldmatrix.sync.aligned.m8n8.x4.shared.b16 {%0,%1,%2,%3}, [%4];"
                 : "=r"(r[0]), "=r"(r[1]), "=r"(r[2]), "=r"(r[3]) : "r"(addr));
}
__device__ __forceinline__ void ldsm_x2(uint32_t* r, uint32_t addr) {
    asm volatile("ldmatrix.sync.aligned.m8n8.x2.shared.b16 {%0,%1}, [%2];"
                 : "=r"(r[0]), "=r"(r[1]) : "r"(addr));
}
__device__ __forceinline__ void mma_f16(float* d, const uint32_t* a, uint32_t b0, uint32_t b1) {
    asm volatile(
        "mma.sync.aligned.m16n8k16.row.col.f32.f16.f16.f32 "
        "{%0,%1,%2,%3}, {%4,%5,%6,%7}, {%8,%9}, {%0,%1,%2,%3};"
        : "+f"(d[0]), "+f"(d[1]), "+f"(d[2]), "+f"(d[3])
        : "r"(a[0]), "r"(a[1]), "r"(a[2]), "r"(a[3]), "r"(b0), "r"(b1));
}
__device__ __forceinline__ void h_split(float v, __half& h, __half& l) {
    h = __float2half_rn(v);
    l = __float2half_rn(v - __half2float(h));
}
__device__ __forceinline__ uint32_t pack2(__half a, __half b) {
    __half2 t;
    t.x = a; t.y = b;
    return *reinterpret_cast<uint32_t*>(&t);
}
// tile layout: row-major rows of 128 f16 (256B = 16 units of 16B), unit XOR-swizzled
__device__ __forceinline__ uint32_t img_off(int n, int k) {
    return (uint32_t)(n * 256 + ((((k >> 3) ^ (n & 7))) << 4) + (k & 7) * 2);
}

// ---------------------------------------------------------------
// prep: transposed + swizzled + fp16-split weight images.
// blockIdx 0=W, 1=W_r, 2=neigh_w.  image row n holds column n of M (k-major).
// ---------------------------------------------------------------
__global__ void __launch_bounds__(256) prep_kernel(const float* __restrict__ W,
                                                   const float* __restrict__ Wr,
                                                   const float* __restrict__ Nw) {
    const float* M = (blockIdx.x == 0) ? W : (blockIdx.x == 1) ? Wr : Nw;
    unsigned char* img = g_Bimg[blockIdx.x];
    for (int idx = threadIdx.x; idx < 128 * 128; idx += 256) {
        int k = idx >> 7, n = idx & 127;
        float v = M[idx];
        __half h, l;
        h_split(v, h, l);
        uint32_t off = img_off(n, k);
        *reinterpret_cast<__half*>(img + off) = h;
        *reinterpret_cast<__half*>(img + 32768 + off) = l;
    }
}

// ---------------------------------------------------------------
// HMMA GEMM: C[M,128] = A[M,128] @ B (image).  fp16 3-term split.
// EPI: 1 = tanh; 2 = store + s1/s2 (a cols 0,1); 3 = store + s_rel + half copy
// 256 threads; CTA tile 128x128, K=128 resident; warp tile 32x64.
// ---------------------------------------------------------------
template <int EPI>
__global__ void __launch_bounds__(256) gemm_hmma(const float* __restrict__ A,
                                                 const unsigned char* __restrict__ Bimg,
                                                 float* __restrict__ C, int M,
                                                 const float* __restrict__ avec,
                                                 float* __restrict__ s1,
                                                 float* __restrict__ s2) {
    extern __shared__ __align__(16) unsigned char dynsm[];
    __shared__ float sred1[128][2];
    __shared__ float sred2[128][2];

    const int tid = threadIdx.x;
    const int wid = tid >> 5;
    const int lane = tid & 31;
    const int row0 = blockIdx.x * 128;

    // ---- B: straight 64KB copy of pre-swizzled hi|lo image ----
    {
        const uint4* srcB = reinterpret_cast<const uint4*>(Bimg);
        uint4* dstB = reinterpret_cast<uint4*>(dynsm + 65536);
#pragma unroll
        for (int i = 0; i < 16; ++i) dstB[tid + i * 256] = srcB[tid + i * 256];
    }
    // ---- A: load fp32, split to fp16 hi/lo, swizzled store ----
#pragma unroll
    for (int it = 0; it < 8; ++it) {
        int idx = tid + it * 256;      // (row, 16B-unit)
        int r = idx >> 4;
        int u = idx & 15;
        int gr = row0 + r;
        float4 v0 = make_float4(0.f, 0.f, 0.f, 0.f);
        float4 v1 = v0;
        if (gr < M) {
            v0 = *reinterpret_cast<const float4*>(A + (size_t)gr * HD + u * 8);
            v1 = *reinterpret_cast<const float4*>(A + (size_t)gr * HD + u * 8 + 4);
        }
        __half h[8], l[8];
        h_split(v0.x, h[0], l[0]); h_split(v0.y, h[1], l[1]);
        h_split(v0.z, h[2], l[2]); h_split(v0.w, h[3], l[3]);
        h_split(v1.x, h[4], l[4]); h_split(v1.y, h[5], l[5]);
        h_split(v1.z, h[6], l[6]); h_split(v1.w, h[7], l[7]);
        uint32_t off = r * 256 + (((u ^ (r & 7))) << 4);
        *reinterpret_cast<uint4*>(dynsm + off) =
            make_uint4(pack2(h[0], h[1]), pack2(h[2], h[3]), pack2(h[4], h[5]), pack2(h[6], h[7]));
        *reinterpret_cast<uint4*>(dynsm + 32768 + off) =
            make_uint4(pack2(l[0], l[1]), pack2(l[2], l[3]), pack2(l[4], l[5]), pack2(l[6], l[7]));
    }
    __syncthreads();

    // ---- compute ----
    const uint32_t sb = smem_u32(dynsm);
    const uint32_t AH = sb, AL = sb + 32768, BH = sb + 65536, BL = sb + 98304;
    const int wr = wid >> 1;
    const int wc = wid & 1;
    const int r0w = wr * 32;
    const int c0w = wc * 64;

    const int rA = lane & 15;
    const int uA = lane >> 4;
    const int axr = rA & 7;
    const int nB = lane & 7;
    const int uB = (lane >> 3) & 1;

    uint32_t arow[2], brow[8];
#pragma unroll
    for (int rb = 0; rb < 2; ++rb) arow[rb] = (uint32_t)(r0w + rb * 16 + rA) * 256;
#pragma unroll
    for (int nb = 0; nb < 8; ++nb) brow[nb] = (uint32_t)(c0w + nb * 8 + nB) * 256;

    float acc[2][8][4];
#pragma unroll
    for (int rb = 0; rb < 2; ++rb)
#pragma unroll
        for (int nb = 0; nb < 8; ++nb) {
            acc[rb][nb][0] = 0.f; acc[rb][nb][1] = 0.f;
            acc[rb][nb][2] = 0.f; acc[rb][nb][3] = 0.f;
        }

#pragma unroll
    for (int kb = 0; kb < 8; ++kb) {
        uint32_t offA = (uint32_t)((2 * kb + uA) ^ axr) << 4;
        uint32_t offB = (uint32_t)((2 * kb + uB) ^ nB) << 4;
        uint32_t ah[2][4], al[2][4];
        ldsm_x4(ah[0], AH + arow[0] + offA);
        ldsm_x4(ah[1], AH + arow[1] + offA);
        ldsm_x4(al[0], AL + arow[0] + offA);
        ldsm_x4(al[1], AL + arow[1] + offA);
#pragma unroll
        for (int nb = 0; nb < 8; ++nb) {
            uint32_t bh[2], bl[2];
            ldsm_x2(bh, BH + brow[nb] + offB);
            ldsm_x2(bl, BL + brow[nb] + offB);
#pragma unroll
            for (int rb = 0; rb < 2; ++rb) {
                mma_f16(acc[rb][nb], ah[rb], bh[0], bh[1]);
                mma_f16(acc[rb][nb], al[rb], bh[0], bh[1]);
                mma_f16(acc[rb][nb], ah[rb], bl[0], bl[1]);
            }
        }
    }

    // ---- epilogue: direct fragment stores (+ fused score dots) ----
    const int tg = lane >> 2, tig = lane & 3;
    float p1[4] = {0.f, 0.f, 0.f, 0.f};
    float p2[4] = {0.f, 0.f, 0.f, 0.f};

#pragma unroll
    for (int rb = 0; rb < 2; ++rb)
#pragma unroll
        for (int nb = 0; nb < 8; ++nb) {
            float* d = acc[rb][nb];
            int c = c0w + nb * 8 + tig * 2;
            if (EPI == 1) {
                d[0] = tanhf(d[0]); d[1] = tanhf(d[1]);
                d[2] = tanhf(d[2]); d[3] = tanhf(d[3]);
            }
            if (EPI == 2) {
                float a1x = avec[c], a1y = avec[c + 1];
                float a2x = avec[128 + c], a2y = avec[129 + c];
                p1[rb * 2]     += d[0] * a1x + d[1] * a1y;
                p2[rb * 2]     += d[0] * a2x + d[1] * a2y;
                p1[rb * 2 + 1] += d[2] * a1x + d[3] * a1y;
                p2[rb * 2 + 1] += d[2] * a2x + d[3] * a2y;
            }
            if (EPI == 3) {
                float a3x = avec[256 + c], a3y = avec[257 + c];
                p1[rb * 2]     += d[0] * a3x + d[1] * a3y;
                p1[rb * 2 + 1] += d[2] * a3x + d[3] * a3y;
            }
            int r1 = row0 + r0w + rb * 16 + tg;
            if (r1 < M) {
                *reinterpret_cast<float2*>(C + (size_t)r1 * HD + c) = make_float2(d[0], d[1]);
                if (EPI == 3)
                    g_hrelh[r1 * 64 + (c >> 1)] = pack2(__float2half_rn(d[0]), __float2half_rn(d[1]));
            }
            if (r1 + 8 < M) {
                *reinterpret_cast<float2*>(C + (size_t)(r1 + 8) * HD + c) = make_float2(d[2], d[3]);
                if (EPI == 3)
                    g_hrelh[(r1 + 8) * 64 + (c >> 1)] = pack2(__float2half_rn(d[2]), __float2half_rn(d[3]));
            }
        }

    if (EPI >= 2) {
#pragma unroll
        for (int rs = 0; rs < 4; ++rs) {
            p1[rs] += __shfl_xor_sync(0xffffffffu, p1[rs], 1);
            p1[rs] += __shfl_xor_sync(0xffffffffu, p1[rs], 2);
            if (EPI == 2) {
                p2[rs] += __shfl_xor_sync(0xffffffffu, p2[rs], 1);
                p2[rs] += __shfl_xor_sync(0xffffffffu, p2[rs], 2);
            }
        }
        if (tig == 0) {
#pragma unroll
            for (int rs = 0; rs < 4; ++rs) {
                int rl = r0w + (rs >> 1) * 16 + (rs & 1) * 8 + tg;
                sred1[rl][wc] = p1[rs];
                if (EPI == 2) sred2[rl][wc] = p2[rs];
            }
        }
        __syncthreads();
        if (tid < 128 && row0 + tid < M) {
            s1[row0 + tid] = sred1[tid][0] + sred1[tid][1];
            if (EPI == 2) s2[row0 + tid] = sred2[tid][0] + sred2[tid][1];
        }
    }
}

// ---------------------------------------------------------------
// Attention: 148 blocks x 1024 threads; h_rel (fp16) + s_rel cached in smem.
// Warp per node; rank-based top-k (set selection only).
// ---------------------------------------------------------------
#define ATTN_SMEM (500 * 64 * 4 + 500 * 4)
__global__ void __launch_bounds__(1024) attn_kernel(const int* __restrict__ src,
                                                    const int* __restrict__ relid) {
    extern __shared__ __align__(16) uint32_t dynattn[];   // [500*64] half2 + [500] float
    __shared__ float ssc[32][32];
    uint32_t* hrelh = dynattn;
    float* srel = reinterpret_cast<float*>(dynattn + 500 * 64);

    const int tid = threadIdx.x;
    const int w = tid >> 5;
    const int lane = tid & 31;

    // cache h_rel (fp16) and s_rel
    for (int i = tid; i < 500 * 16; i += 1024)
        reinterpret_cast<uint4*>(hrelh)[i] = reinterpret_cast<const uint4*>(g_hrelh)[i];
    for (int i = tid; i < 500; i += 1024) srel[i] = g_srel[i];
    __syncthreads();

    for (int n = blockIdx.x * 32 + w; n < NENT; n += 148 * 32) {
        int s_id = src[(size_t)n * DEG + lane];
        int r_id = relid[(size_t)n * DEG + lane];
        float sc = g_ssrc[s_id] + g_sdst[n] + srel[r_id];
        sc = sc > 0.f ? sc : 0.2f * sc;  // leaky_relu 0.2

        ssc[w][lane] = sc;
        __syncwarp();
        int rank = 0;
#pragma unroll
        for (int j = 0; j < 32; ++j) {
            float o = ssc[w][j];
            rank += (o > sc) || (o == sc && j < lane);
        }
        __syncwarp();
        bool sel = rank < TOPK;

        float m = sc;
#pragma unroll
        for (int o = 16; o; o >>= 1) m = fmaxf(m, __shfl_xor_sync(0xffffffffu, m, o));
        float p = sel ? __expf(sc - m) : 0.f;
        float s = p;
#pragma unroll
        for (int o = 16; o; o >>= 1) s += __shfl_xor_sync(0xffffffffu, s, o);
        float attn = p / s;

        unsigned mask = __ballot_sync(0xffffffffu, sel);
        float4 acc = make_float4(0.f, 0.f, 0.f, 0.f);
#pragma unroll
        for (int k = 0; k < TOPK; ++k) {
            int l = __ffs(mask) - 1;
            mask &= mask - 1;
            float wgt = __shfl_sync(0xffffffffu, attn, l);
            int sk = __shfl_sync(0xffffffffu, s_id, l);
            int rk = __shfl_sync(0xffffffffu, r_id, l);
            float4 hv = *reinterpret_cast<const float4*>(g_hnode + (size_t)sk * HD + lane * 4);
            uint2 hr = *reinterpret_cast<const uint2*>(hrelh + rk * 64 + lane * 2);
            float2 f0 = __half22float2(*reinterpret_cast<__half2*>(&hr.x));
            float2 f1 = __half22float2(*reinterpret_cast<__half2*>(&hr.y));
            acc.x += wgt * (hv.x + f0.x);
            acc.y += wgt * (hv.y + f0.y);
            acc.z += wgt * (hv.z + f1.x);
            acc.w += wgt * (hv.w + f1.y);
        }
        *reinterpret_cast<float4*>(g_neigh + (size_t)n * HD + lane * 4) = acc;
    }
}

// ---------------------------------------------------------------
extern "C" void kernel_launch(void* const* d_in, const int* in_sizes, int n_in,
                              void* d_out, int out_size) {
    const float* ent   = (const float*)d_in[0];
    const float* rel   = (const float*)d_in[1];
    const float* W     = (const float*)d_in[2];
    const float* Wr    = (const float*)d_in[3];
    const float* a     = (const float*)d_in[4];
    const float* nw    = (const float*)d_in[5];
    const int*   src   = (const int*)d_in[6];
    const int*   relid = (const int*)d_in[7];
    float* out = (float*)d_out;

    float *p_hnode, *p_hrel, *p_neigh, *p_ssrc, *p_sdst, *p_srel;
    unsigned char* p_img;
    cudaGetSymbolAddress((void**)&p_hnode, g_hnode);
    cudaGetSymbolAddress((void**)&p_hrel, g_hrel);
    cudaGetSymbolAddress((void**)&p_neigh, g_neigh);
    cudaGetSymbolAddress((void**)&p_ssrc, g_ssrc);
    cudaGetSymbolAddress((void**)&p_sdst, g_sdst);
    cudaGetSymbolAddress((void**)&p_srel, g_srel);
    cudaGetSymbolAddress((void**)&p_img, g_Bimg);

    const int SMEM = 131072;
    cudaFuncSetAttribute(gemm_hmma<1>, cudaFuncAttributeMaxDynamicSharedMemorySize, SMEM);
    cudaFuncSetAttribute(gemm_hmma<2>, cudaFuncAttributeMaxDynamicSharedMemorySize, SMEM);
    cudaFuncSetAttribute(gemm_hmma<3>, cudaFuncAttributeMaxDynamicSharedMemorySize, SMEM);
    cudaFuncSetAttribute(attn_kernel, cudaFuncAttributeMaxDynamicSharedMemorySize, ATTN_SMEM);

    prep_kernel<<<3, 256>>>(W, Wr, nw);

    const int NB = (NENT + 127) / 128;
    // h_node = ent @ W  (+ fused s_src/s_dst)
    gemm_hmma<2><<<NB, 256, SMEM>>>(ent, p_img, p_hnode, NENT, a, p_ssrc, p_sdst);
    // h_rel = rel @ W_r (+ fused s_rel + fp16 copy)
    gemm_hmma<3><<<(NRELN + 127) / 128, 256, SMEM>>>(rel, p_img + 65536, p_hrel, NRELN, a, p_srel, nullptr);
    // attention + aggregation (h_rel, s_rel cached in smem)
    attn_kernel<<<148, 1024, ATTN_SMEM>>>(src, relid);
    // out = tanh(neigh @ neigh_w)
    gemm_hmma<1><<<NB, 256, SMEM>>>(p_neigh, p_img + 2 * 65536, out, NENT, nullptr, nullptr, nullptr);
}

// round 5
// speedup vs baseline: 1.1705x; 1.1705x over previous
#include <cuda_runtime.h>
#include <cuda_fp16.h>
#include <math.h>
#include <stdint.h>

#define NENT 150000
#define NRELN 500
#define HD 128
#define DEG 32
#define TOPK 10

// -------- scratch (device globals; no allocation allowed) --------
__device__ float g_hnode[150016 * 128];
__device__ float g_neigh[150016 * 128];
__device__ float g_hrel[512 * 128];
__device__ uint32_t g_hnodeh[150016 * 64];  // h_node as half2 pairs
__device__ uint32_t g_hrelh[512 * 64];      // h_rel  as half2 pairs
__device__ float g_ssrc[150016];
__device__ float g_sdst[150016];
__device__ float g_srel[512];
// pre-transposed + swizzled fp16-split weight images: [matrix][hi 32KB | lo 32KB]
__device__ __align__(16) unsigned char g_Bimg[3][65536];

// ================= helpers =================
__device__ __forceinline__ uint32_t smem_u32(const void* p) {
    uint32_t a;
    asm("{ .reg .u64 t; cvta.to.shared.u64 t, %1; cvt.u32.u64 %0, t; }" : "=r"(a) : "l"(p));
    return a;
}
__device__ __forceinline__ void ldsm_x4(uint32_t* r, uint32_t addr) {
    asm volatile("ldmatrix.sync.aligned.m8n8.x4.shared.b16 {%0,%1,%2,%3}, [%4];"
                 : "=r"(r[0]), "=r"(r[1]), "=r"(r[2]), "=r"(r[3]) : "r"(addr));
}
__device__ __forceinline__ void ldsm_x2(uint32_t* r, uint32_t addr) {
    asm volatile("ldmatrix.sync.aligned.m8n8.x2.shared.b16 {%0,%1}, [%2];"
                 : "=r"(r[0]), "=r"(r[1]) : "r"(addr));
}
__device__ __forceinline__ void mma_f16(float* d, const uint32_t* a, uint32_t b0, uint32_t b1) {
    asm volatile(
        "mma.sync.aligned.m16n8k16.row.col.f32.f16.f16.f32 "
        "{%0,%1,%2,%3}, {%4,%5,%6,%7}, {%8,%9}, {%0,%1,%2,%3};"
        : "+f"(d[0]), "+f"(d[1]), "+f"(d[2]), "+f"(d[3])
        : "r"(a[0]), "r"(a[1]), "r"(a[2]), "r"(a[3]), "r"(b0), "r"(b1));
}
__device__ __forceinline__ void h_split(float v, __half& h, __half& l) {
    h = __float2half_rn(v);
    l = __float2half_rn(v - __half2float(h));
}
__device__ __forceinline__ uint32_t pack2(__half a, __half b) {
    __half2 t;
    t.x = a; t.y = b;
    return *reinterpret_cast<uint32_t*>(&t);
}
// tile layout: row-major rows of 128 f16 (256B = 16 units of 16B), unit XOR-swizzled
__device__ __forceinline__ uint32_t img_off(int n, int k) {
    return (uint32_t)(n * 256 + ((((k >> 3) ^ (n & 7))) << 4) + (k & 7) * 2);
}

// ---------------------------------------------------------------
// prep: transposed + swizzled + fp16-split weight images.
// ---------------------------------------------------------------
__global__ void __launch_bounds__(256) prep_kernel(const float* __restrict__ W,
                                                   const float* __restrict__ Wr,
                                                   const float* __restrict__ Nw) {
    const float* M = (blockIdx.x == 0) ? W : (blockIdx.x == 1) ? Wr : Nw;
    unsigned char* img = g_Bimg[blockIdx.x];
    for (int idx = threadIdx.x; idx < 128 * 128; idx += 256) {
        int k = idx >> 7, n = idx & 127;
        float v = M[idx];
        __half h, l;
        h_split(v, h, l);
        uint32_t off = img_off(n, k);
        *reinterpret_cast<__half*>(img + off) = h;
        *reinterpret_cast<__half*>(img + 32768 + off) = l;
    }
}

// ---------------------------------------------------------------
// HMMA GEMM: C[M,128] = A[M,128] @ B (image).  fp16 3-term split.
// EPI: 1 = tanh; 2 = store + s1/s2 + fp16 copy to g_hnodeh;
//      3 = store + s_rel + fp16 copy to g_hrelh
// ---------------------------------------------------------------
template <int EPI>
__global__ void __launch_bounds__(256) gemm_hmma(const float* __restrict__ A,
                                                 const unsigned char* __restrict__ Bimg,
                                                 float* __restrict__ C, int M,
                                                 const float* __restrict__ avec,
                                                 float* __restrict__ s1,
                                                 float* __restrict__ s2) {
    extern __shared__ __align__(16) unsigned char dynsm[];
    __shared__ float sred1[128][2];
    __shared__ float sred2[128][2];

    const int tid = threadIdx.x;
    const int wid = tid >> 5;
    const int lane = tid & 31;
    const int row0 = blockIdx.x * 128;

    // ---- B: straight 64KB copy of pre-swizzled hi|lo image ----
    {
        const uint4* srcB = reinterpret_cast<const uint4*>(Bimg);
        uint4* dstB = reinterpret_cast<uint4*>(dynsm + 65536);
#pragma unroll
        for (int i = 0; i < 16; ++i) dstB[tid + i * 256] = srcB[tid + i * 256];
    }
    // ---- A: load fp32, split to fp16 hi/lo, swizzled store ----
#pragma unroll
    for (int it = 0; it < 8; ++it) {
        int idx = tid + it * 256;
        int r = idx >> 4;
        int u = idx & 15;
        int gr = row0 + r;
        float4 v0 = make_float4(0.f, 0.f, 0.f, 0.f);
        float4 v1 = v0;
        if (gr < M) {
            v0 = *reinterpret_cast<const float4*>(A + (size_t)gr * HD + u * 8);
            v1 = *reinterpret_cast<const float4*>(A + (size_t)gr * HD + u * 8 + 4);
        }
        __half h[8], l[8];
        h_split(v0.x, h[0], l[0]); h_split(v0.y, h[1], l[1]);
        h_split(v0.z, h[2], l[2]); h_split(v0.w, h[3], l[3]);
        h_split(v1.x, h[4], l[4]); h_split(v1.y, h[5], l[5]);
        h_split(v1.z, h[6], l[6]); h_split(v1.w, h[7], l[7]);
        uint32_t off = r * 256 + (((u ^ (r & 7))) << 4);
        *reinterpret_cast<uint4*>(dynsm + off) =
            make_uint4(pack2(h[0], h[1]), pack2(h[2], h[3]), pack2(h[4], h[5]), pack2(h[6], h[7]));
        *reinterpret_cast<uint4*>(dynsm + 32768 + off) =
            make_uint4(pack2(l[0], l[1]), pack2(l[2], l[3]), pack2(l[4], l[5]), pack2(l[6], l[7]));
    }
    __syncthreads();

    // ---- compute ----
    const uint32_t sb = smem_u32(dynsm);
    const uint32_t AH = sb, AL = sb + 32768, BH = sb + 65536, BL = sb + 98304;
    const int wr = wid >> 1;
    const int wc = wid & 1;
    const int r0w = wr * 32;
    const int c0w = wc * 64;

    const int rA = lane & 15;
    const int uA = lane >> 4;
    const int axr = rA & 7;
    const int nB = lane & 7;
    const int uB = (lane >> 3) & 1;

    uint32_t arow[2], brow[8];
#pragma unroll
    for (int rb = 0; rb < 2; ++rb) arow[rb] = (uint32_t)(r0w + rb * 16 + rA) * 256;
#pragma unroll
    for (int nb = 0; nb < 8; ++nb) brow[nb] = (uint32_t)(c0w + nb * 8 + nB) * 256;

    float acc[2][8][4];
#pragma unroll
    for (int rb = 0; rb < 2; ++rb)
#pragma unroll
        for (int nb = 0; nb < 8; ++nb) {
            acc[rb][nb][0] = 0.f; acc[rb][nb][1] = 0.f;
            acc[rb][nb][2] = 0.f; acc[rb][nb][3] = 0.f;
        }

#pragma unroll
    for (int kb = 0; kb < 8; ++kb) {
        uint32_t offA = (uint32_t)((2 * kb + uA) ^ axr) << 4;
        uint32_t offB = (uint32_t)((2 * kb + uB) ^ nB) << 4;
        uint32_t ah[2][4], al[2][4];
        ldsm_x4(ah[0], AH + arow[0] + offA);
        ldsm_x4(ah[1], AH + arow[1] + offA);
        ldsm_x4(al[0], AL + arow[0] + offA);
        ldsm_x4(al[1], AL + arow[1] + offA);
#pragma unroll
        for (int nb = 0; nb < 8; ++nb) {
            uint32_t bh[2], bl[2];
            ldsm_x2(bh, BH + brow[nb] + offB);
            ldsm_x2(bl, BL + brow[nb] + offB);
#pragma unroll
            for (int rb = 0; rb < 2; ++rb) {
                mma_f16(acc[rb][nb], ah[rb], bh[0], bh[1]);
                mma_f16(acc[rb][nb], al[rb], bh[0], bh[1]);
                mma_f16(acc[rb][nb], ah[rb], bl[0], bl[1]);
            }
        }
    }

    // ---- epilogue: direct fragment stores (+ fused score dots + fp16 copies) ----
    const int tg = lane >> 2, tig = lane & 3;
    float p1[4] = {0.f, 0.f, 0.f, 0.f};
    float p2[4] = {0.f, 0.f, 0.f, 0.f};

#pragma unroll
    for (int rb = 0; rb < 2; ++rb)
#pragma unroll
        for (int nb = 0; nb < 8; ++nb) {
            float* d = acc[rb][nb];
            int c = c0w + nb * 8 + tig * 2;
            if (EPI == 1) {
                d[0] = tanhf(d[0]); d[1] = tanhf(d[1]);
                d[2] = tanhf(d[2]); d[3] = tanhf(d[3]);
            }
            if (EPI == 2) {
                float a1x = avec[c], a1y = avec[c + 1];
                float a2x = avec[128 + c], a2y = avec[129 + c];
                p1[rb * 2]     += d[0] * a1x + d[1] * a1y;
                p2[rb * 2]     += d[0] * a2x + d[1] * a2y;
                p1[rb * 2 + 1] += d[2] * a1x + d[3] * a1y;
                p2[rb * 2 + 1] += d[2] * a2x + d[3] * a2y;
            }
            if (EPI == 3) {
                float a3x = avec[256 + c], a3y = avec[257 + c];
                p1[rb * 2]     += d[0] * a3x + d[1] * a3y;
                p1[rb * 2 + 1] += d[2] * a3x + d[3] * a3y;
            }
            int r1 = row0 + r0w + rb * 16 + tg;
            if (r1 < M) {
                *reinterpret_cast<float2*>(C + (size_t)r1 * HD + c) = make_float2(d[0], d[1]);
                if (EPI == 2)
                    g_hnodeh[(size_t)r1 * 64 + (c >> 1)] = pack2(__float2half_rn(d[0]), __float2half_rn(d[1]));
                if (EPI == 3)
                    g_hrelh[r1 * 64 + (c >> 1)] = pack2(__float2half_rn(d[0]), __float2half_rn(d[1]));
            }
            if (r1 + 8 < M) {
                *reinterpret_cast<float2*>(C + (size_t)(r1 + 8) * HD + c) = make_float2(d[2], d[3]);
                if (EPI == 2)
                    g_hnodeh[(size_t)(r1 + 8) * 64 + (c >> 1)] = pack2(__float2half_rn(d[2]), __float2half_rn(d[3]));
                if (EPI == 3)
                    g_hrelh[(r1 + 8) * 64 + (c >> 1)] = pack2(__float2half_rn(d[2]), __float2half_rn(d[3]));
            }
        }

    if (EPI >= 2) {
#pragma unroll
        for (int rs = 0; rs < 4; ++rs) {
            p1[rs] += __shfl_xor_sync(0xffffffffu, p1[rs], 1);
            p1[rs] += __shfl_xor_sync(0xffffffffu, p1[rs], 2);
            if (EPI == 2) {
                p2[rs] += __shfl_xor_sync(0xffffffffu, p2[rs], 1);
                p2[rs] += __shfl_xor_sync(0xffffffffu, p2[rs], 2);
            }
        }
        if (tig == 0) {
#pragma unroll
            for (int rs = 0; rs < 4; ++rs) {
                int rl = r0w + (rs >> 1) * 16 + (rs & 1) * 8 + tg;
                sred1[rl][wc] = p1[rs];
                if (EPI == 2) sred2[rl][wc] = p2[rs];
            }
        }
        __syncthreads();
        if (tid < 128 && row0 + tid < M) {
            s1[row0 + tid] = sred1[tid][0] + sred1[tid][1];
            if (EPI == 2) s2[row0 + tid] = sred2[tid][0] + sred2[tid][1];
        }
    }
}

// ---------------------------------------------------------------
// Attention: warp per node; fp16 gathers for h_node AND h_rel.
// Rank-based top-k (set selection only).
// ---------------------------------------------------------------
__global__ void __launch_bounds__(256) attn_kernel(const int* __restrict__ src,
                                                   const int* __restrict__ relid) {
    __shared__ float ssc[8][32];
    int warp = (blockIdx.x * blockDim.x + threadIdx.x) >> 5;
    int w = threadIdx.x >> 5;
    int lane = threadIdx.x & 31;
    if (warp >= NENT) return;
    const int n = warp;

    int s_id = src[(size_t)n * DEG + lane];
    int r_id = relid[(size_t)n * DEG + lane];
    float sc = g_ssrc[s_id] + g_sdst[n] + g_srel[r_id];
    sc = sc > 0.f ? sc : 0.2f * sc;  // leaky_relu 0.2

    ssc[w][lane] = sc;
    __syncwarp();
    int rank = 0;
#pragma unroll
    for (int j = 0; j < 32; ++j) {
        float o = ssc[w][j];
        rank += (o > sc) || (o == sc && j < lane);
    }
    bool sel = rank < TOPK;

    float m = sc;
#pragma unroll
    for (int o = 16; o; o >>= 1) m = fmaxf(m, __shfl_xor_sync(0xffffffffu, m, o));
    float p = sel ? __expf(sc - m) : 0.f;
    float s = p;
#pragma unroll
    for (int o = 16; o; o >>= 1) s += __shfl_xor_sync(0xffffffffu, s, o);
    float attn = p / s;

    unsigned mask = __ballot_sync(0xffffffffu, sel);
    float4 acc = make_float4(0.f, 0.f, 0.f, 0.f);
#pragma unroll
    for (int k = 0; k < TOPK; ++k) {
        int l = __ffs(mask) - 1;
        mask &= mask - 1;
        float wgt = __shfl_sync(0xffffffffu, attn, l);
        int sk = __shfl_sync(0xffffffffu, s_id, l);
        int rk = __shfl_sync(0xffffffffu, r_id, l);
        uint2 hn = *reinterpret_cast<const uint2*>(g_hnodeh + (size_t)sk * 64 + lane * 2);
        uint2 hr = *reinterpret_cast<const uint2*>(g_hrelh + rk * 64 + lane * 2);
        float2 n0 = __half22float2(*reinterpret_cast<__half2*>(&hn.x));
        float2 n1 = __half22float2(*reinterpret_cast<__half2*>(&hn.y));
        float2 r0 = __half22float2(*reinterpret_cast<__half2*>(&hr.x));
        float2 r1 = __half22float2(*reinterpret_cast<__half2*>(&hr.y));
        acc.x += wgt * (n0.x + r0.x);
        acc.y += wgt * (n0.y + r0.y);
        acc.z += wgt * (n1.x + r1.x);
        acc.w += wgt * (n1.y + r1.y);
    }
    *reinterpret_cast<float4*>(g_neigh + (size_t)n * HD + lane * 4) = acc;
}

// ---------------------------------------------------------------
extern "C" void kernel_launch(void* const* d_in, const int* in_sizes, int n_in,
                              void* d_out, int out_size) {
    const float* ent   = (const float*)d_in[0];
    const float* rel   = (const float*)d_in[1];
    const float* W     = (const float*)d_in[2];
    const float* Wr    = (const float*)d_in[3];
    const float* a     = (const float*)d_in[4];
    const float* nw    = (const float*)d_in[5];
    const int*   src   = (const int*)d_in[6];
    const int*   relid = (const int*)d_in[7];
    float* out = (float*)d_out;

    float *p_hnode, *p_hrel, *p_neigh, *p_ssrc, *p_sdst, *p_srel;
    unsigned char* p_img;
    cudaGetSymbolAddress((void**)&p_hnode, g_hnode);
    cudaGetSymbolAddress((void**)&p_hrel, g_hrel);
    cudaGetSymbolAddress((void**)&p_neigh, g_neigh);
    cudaGetSymbolAddress((void**)&p_ssrc, g_ssrc);
    cudaGetSymbolAddress((void**)&p_sdst, g_sdst);
    cudaGetSymbolAddress((void**)&p_srel, g_srel);
    cudaGetSymbolAddress((void**)&p_img, g_Bimg);

    const int SMEM = 131072;
    cudaFuncSetAttribute(gemm_hmma<1>, cudaFuncAttributeMaxDynamicSharedMemorySize, SMEM);
    cudaFuncSetAttribute(gemm_hmma<2>, cudaFuncAttributeMaxDynamicSharedMemorySize, SMEM);
    cudaFuncSetAttribute(gemm_hmma<3>, cudaFuncAttributeMaxDynamicSharedMemorySize, SMEM);

    prep_kernel<<<3, 256>>>(W, Wr, nw);

    const int NB = (NENT + 127) / 128;
    // h_node = ent @ W  (+ fused s_src/s_dst + fp16 copy)
    gemm_hmma<2><<<NB, 256, SMEM>>>(ent, p_img, p_hnode, NENT, a, p_ssrc, p_sdst);
    // h_rel = rel @ W_r (+ fused s_rel + fp16 copy)
    gemm_hmma<3><<<(NRELN + 127) / 128, 256, SMEM>>>(rel, p_img + 65536, p_hrel, NRELN, a, p_srel, nullptr);
    // attention + aggregation (fp16 gathers)
    attn_kernel<<<(NENT * 32 + 255) / 256, 256>>>(src, relid);
    // out = tanh(neigh @ neigh_w)
    gemm_hmma<1><<<NB, 256, SMEM>>>(p_neigh, p_img + 2 * 65536, out, NENT, nullptr, nullptr, nullptr);
}

// round 6
// speedup vs baseline: 1.2821x; 1.0953x over previous
#include <cuda_runtime.h>
#include <cuda_fp16.h>
#include <math.h>
#include <stdint.h>

#define NENT 150000
#define NRELN 500
#define HD 128
#define DEG 32
#define TOPK 10

// -------- scratch (device globals; no allocation allowed) --------
__device__ float g_neigh[150016 * 128];
__device__ uint32_t g_hnodeh[150016 * 64];  // h_node as half2 pairs
__device__ uint32_t g_hrelh[512 * 64];      // h_rel  as half2 pairs
__device__ float g_ssrc[150016];
__device__ float g_sdst[150016];
__device__ float g_srel[512];
// pre-transposed + swizzled fp16-split weight images: [matrix][hi 32KB | lo 32KB]
__device__ __align__(16) unsigned char g_Bimg[3][65536];

// ================= helpers =================
__device__ __forceinline__ uint32_t smem_u32(const void* p) {
    uint32_t a;
    asm("{ .reg .u64 t; cvta.to.shared.u64 t, %1; cvt.u32.u64 %0, t; }" : "=r"(a) : "l"(p));
    return a;
}
__device__ __forceinline__ void ldsm_x4(uint32_t* r, uint32_t addr) {
    asm volatile("ldmatrix.sync.aligned.m8n8.x4.shared.b16 {%0,%1,%2,%3}, [%4];"
                 : "=r"(r[0]), "=r"(r[1]), "=r"(r[2]), "=r"(r[3]) : "r"(addr));
}
__device__ __forceinline__ void ldsm_x2(uint32_t* r, uint32_t addr) {
    asm volatile("ldmatrix.sync.aligned.m8n8.x2.shared.b16 {%0,%1}, [%2];"
                 : "=r"(r[0]), "=r"(r[1]) : "r"(addr));
}
__device__ __forceinline__ void mma_f16(float* d, const uint32_t* a, uint32_t b0, uint32_t b1) {
    asm volatile(
        "mma.sync.aligned.m16n8k16.row.col.f32.f16.f16.f32 "
        "{%0,%1,%2,%3}, {%4,%5,%6,%7}, {%8,%9}, {%0,%1,%2,%3};"
        : "+f"(d[0]), "+f"(d[1]), "+f"(d[2]), "+f"(d[3])
        : "r"(a[0]), "r"(a[1]), "r"(a[2]), "r"(a[3]), "r"(b0), "r"(b1));
}
__device__ __forceinline__ void h_split(float v, __half& h, __half& l) {
    h = __float2half_rn(v);
    l = __float2half_rn(v - __half2float(h));
}
__device__ __forceinline__ uint32_t pack2(__half a, __half b) {
    __half2 t;
    t.x = a; t.y = b;
    return *reinterpret_cast<uint32_t*>(&t);
}
// tile layout: row-major rows of 128 f16 (256B = 16 units of 16B), unit XOR-swizzled
__device__ __forceinline__ uint32_t img_off(int n, int k) {
    return (uint32_t)(n * 256 + ((((k >> 3) ^ (n & 7))) << 4) + (k & 7) * 2);
}

// ---------------------------------------------------------------
// prep: transposed + swizzled + fp16-split weight images.
// ---------------------------------------------------------------
__global__ void __launch_bounds__(256) prep_kernel(const float* __restrict__ W,
                                                   const float* __restrict__ Wr,
                                                   const float* __restrict__ Nw) {
    const float* M = (blockIdx.x == 0) ? W : (blockIdx.x == 1) ? Wr : Nw;
    unsigned char* img = g_Bimg[blockIdx.x];
    for (int idx = threadIdx.x; idx < 128 * 128; idx += 256) {
        int k = idx >> 7, n = idx & 127;
        float v = M[idx];
        __half h, l;
        h_split(v, h, l);
        uint32_t off = img_off(n, k);
        *reinterpret_cast<__half*>(img + off) = h;
        *reinterpret_cast<__half*>(img + 32768 + off) = l;
    }
}

// ---------------------------------------------------------------
// HMMA GEMM: D = A[M,128] @ B (image).  fp16 3-term split.
// EPI: 1 = tanh -> C fp32;
//      2 = fp16 image to g_hnodeh + fused s1/s2 (a cols 0,1)  [no fp32 C]
//      3 = fp16 image to g_hrelh  + fused s_rel (a col 2)     [no fp32 C]
// ---------------------------------------------------------------
template <int EPI>
__global__ void __launch_bounds__(256) gemm_hmma(const float* __restrict__ A,
                                                 const unsigned char* __restrict__ Bimg,
                                                 float* __restrict__ C, int M,
                                                 const float* __restrict__ avec,
                                                 float* __restrict__ s1,
                                                 float* __restrict__ s2) {
    extern __shared__ __align__(16) unsigned char dynsm[];
    __shared__ float sred1[128][2];
    __shared__ float sred2[128][2];

    const int tid = threadIdx.x;
    const int wid = tid >> 5;
    const int lane = tid & 31;
    const int row0 = blockIdx.x * 128;

    // ---- B: straight 64KB copy of pre-swizzled hi|lo image ----
    {
        const uint4* srcB = reinterpret_cast<const uint4*>(Bimg);
        uint4* dstB = reinterpret_cast<uint4*>(dynsm + 65536);
#pragma unroll
        for (int i = 0; i < 16; ++i) dstB[tid + i * 256] = srcB[tid + i * 256];
    }
    // ---- A: load fp32, split to fp16 hi/lo, swizzled store ----
#pragma unroll
    for (int it = 0; it < 8; ++it) {
        int idx = tid + it * 256;
        int r = idx >> 4;
        int u = idx & 15;
        int gr = row0 + r;
        float4 v0 = make_float4(0.f, 0.f, 0.f, 0.f);
        float4 v1 = v0;
        if (gr < M) {
            v0 = *reinterpret_cast<const float4*>(A + (size_t)gr * HD + u * 8);
            v1 = *reinterpret_cast<const float4*>(A + (size_t)gr * HD + u * 8 + 4);
        }
        __half h[8], l[8];
        h_split(v0.x, h[0], l[0]); h_split(v0.y, h[1], l[1]);
        h_split(v0.z, h[2], l[2]); h_split(v0.w, h[3], l[3]);
        h_split(v1.x, h[4], l[4]); h_split(v1.y, h[5], l[5]);
        h_split(v1.z, h[6], l[6]); h_split(v1.w, h[7], l[7]);
        uint32_t off = r * 256 + (((u ^ (r & 7))) << 4);
        *reinterpret_cast<uint4*>(dynsm + off) =
            make_uint4(pack2(h[0], h[1]), pack2(h[2], h[3]), pack2(h[4], h[5]), pack2(h[6], h[7]));
        *reinterpret_cast<uint4*>(dynsm + 32768 + off) =
            make_uint4(pack2(l[0], l[1]), pack2(l[2], l[3]), pack2(l[4], l[5]), pack2(l[6], l[7]));
    }
    __syncthreads();

    // ---- compute ----
    const uint32_t sb = smem_u32(dynsm);
    const uint32_t AH = sb, AL = sb + 32768, BH = sb + 65536, BL = sb + 98304;
    const int wr = wid >> 1;
    const int wc = wid & 1;
    const int r0w = wr * 32;
    const int c0w = wc * 64;

    const int rA = lane & 15;
    const int uA = lane >> 4;
    const int axr = rA & 7;
    const int nB = lane & 7;
    const int uB = (lane >> 3) & 1;

    uint32_t arow[2], brow[8];
#pragma unroll
    for (int rb = 0; rb < 2; ++rb) arow[rb] = (uint32_t)(r0w + rb * 16 + rA) * 256;
#pragma unroll
    for (int nb = 0; nb < 8; ++nb) brow[nb] = (uint32_t)(c0w + nb * 8 + nB) * 256;

    float acc[2][8][4];
#pragma unroll
    for (int rb = 0; rb < 2; ++rb)
#pragma unroll
        for (int nb = 0; nb < 8; ++nb) {
            acc[rb][nb][0] = 0.f; acc[rb][nb][1] = 0.f;
            acc[rb][nb][2] = 0.f; acc[rb][nb][3] = 0.f;
        }

#pragma unroll
    for (int kb = 0; kb < 8; ++kb) {
        uint32_t offA = (uint32_t)((2 * kb + uA) ^ axr) << 4;
        uint32_t offB = (uint32_t)((2 * kb + uB) ^ nB) << 4;
        uint32_t ah[2][4], al[2][4];
        ldsm_x4(ah[0], AH + arow[0] + offA);
        ldsm_x4(ah[1], AH + arow[1] + offA);
        ldsm_x4(al[0], AL + arow[0] + offA);
        ldsm_x4(al[1], AL + arow[1] + offA);
#pragma unroll
        for (int nb = 0; nb < 8; ++nb) {
            uint32_t bh[2], bl[2];
            ldsm_x2(bh, BH + brow[nb] + offB);
            ldsm_x2(bl, BL + brow[nb] + offB);
#pragma unroll
            for (int rb = 0; rb < 2; ++rb) {
                mma_f16(acc[rb][nb], ah[rb], bh[0], bh[1]);
                mma_f16(acc[rb][nb], al[rb], bh[0], bh[1]);
                mma_f16(acc[rb][nb], ah[rb], bl[0], bl[1]);
            }
        }
    }

    // ---- epilogue ----
    const int tg = lane >> 2, tig = lane & 3;
    float p1[4] = {0.f, 0.f, 0.f, 0.f};
    float p2[4] = {0.f, 0.f, 0.f, 0.f};

#pragma unroll
    for (int rb = 0; rb < 2; ++rb)
#pragma unroll
        for (int nb = 0; nb < 8; ++nb) {
            float* d = acc[rb][nb];
            int c = c0w + nb * 8 + tig * 2;
            int r1 = row0 + r0w + rb * 16 + tg;
            if (EPI == 1) {
                float2 lo = make_float2(tanhf(d[0]), tanhf(d[1]));
                float2 hi = make_float2(tanhf(d[2]), tanhf(d[3]));
                if (r1 < M)
                    *reinterpret_cast<float2*>(C + (size_t)r1 * HD + c) = lo;
                if (r1 + 8 < M)
                    *reinterpret_cast<float2*>(C + (size_t)(r1 + 8) * HD + c) = hi;
            }
            if (EPI == 2) {
                float a1x = avec[c], a1y = avec[c + 1];
                float a2x = avec[128 + c], a2y = avec[129 + c];
                p1[rb * 2]     += d[0] * a1x + d[1] * a1y;
                p2[rb * 2]     += d[0] * a2x + d[1] * a2y;
                p1[rb * 2 + 1] += d[2] * a1x + d[3] * a1y;
                p2[rb * 2 + 1] += d[2] * a2x + d[3] * a2y;
                if (r1 < M)
                    g_hnodeh[(size_t)r1 * 64 + (c >> 1)] = pack2(__float2half_rn(d[0]), __float2half_rn(d[1]));
                if (r1 + 8 < M)
                    g_hnodeh[(size_t)(r1 + 8) * 64 + (c >> 1)] = pack2(__float2half_rn(d[2]), __float2half_rn(d[3]));
            }
            if (EPI == 3) {
                float a3x = avec[256 + c], a3y = avec[257 + c];
                p1[rb * 2]     += d[0] * a3x + d[1] * a3y;
                p1[rb * 2 + 1] += d[2] * a3x + d[3] * a3y;
                if (r1 < M)
                    g_hrelh[r1 * 64 + (c >> 1)] = pack2(__float2half_rn(d[0]), __float2half_rn(d[1]));
                if (r1 + 8 < M)
                    g_hrelh[(r1 + 8) * 64 + (c >> 1)] = pack2(__float2half_rn(d[2]), __float2half_rn(d[3]));
            }
        }

    if (EPI >= 2) {
#pragma unroll
        for (int rs = 0; rs < 4; ++rs) {
            p1[rs] += __shfl_xor_sync(0xffffffffu, p1[rs], 1);
            p1[rs] += __shfl_xor_sync(0xffffffffu, p1[rs], 2);
            if (EPI == 2) {
                p2[rs] += __shfl_xor_sync(0xffffffffu, p2[rs], 1);
                p2[rs] += __shfl_xor_sync(0xffffffffu, p2[rs], 2);
            }
        }
        if (tig == 0) {
#pragma unroll
            for (int rs = 0; rs < 4; ++rs) {
                int rl = r0w + (rs >> 1) * 16 + (rs & 1) * 8 + tg;
                sred1[rl][wc] = p1[rs];
                if (EPI == 2) sred2[rl][wc] = p2[rs];
            }
        }
        __syncthreads();
        if (tid < 128 && row0 + tid < M) {
            s1[row0 + tid] = sred1[tid][0] + sred1[tid][1];
            if (EPI == 2) s2[row0 + tid] = sred2[tid][0] + sred2[tid][1];
        }
    }
}

// ---------------------------------------------------------------
// Attention: warp per node; fp16 gathers; rank-based top-k;
// no-max softmax (scores are O(10), exp safe in fp32);
// packed (src|rel) index shuffles.
// ---------------------------------------------------------------
__global__ void __launch_bounds__(256) attn_kernel(const int* __restrict__ src,
                                                   const int* __restrict__ relid) {
    __shared__ float ssc[8][32];
    int warp = (blockIdx.x * blockDim.x + threadIdx.x) >> 5;
    int w = threadIdx.x >> 5;
    int lane = threadIdx.x & 31;
    if (warp >= NENT) return;
    const int n = warp;

    int s_id = src[(size_t)n * DEG + lane];
    int r_id = relid[(size_t)n * DEG + lane];
    float sc = g_ssrc[s_id] + g_sdst[n] + g_srel[r_id];
    sc = sc > 0.f ? sc : 0.2f * sc;  // leaky_relu 0.2

    ssc[w][lane] = sc;
    __syncwarp();
    int rank = 0;
#pragma unroll
    for (int j = 0; j < 32; ++j) {
        float o = ssc[w][j];
        rank += (o > sc) || (o == sc && j < lane);
    }
    bool sel = rank < TOPK;

    // softmax over selected, no max shift (|sc| small; exp safe in fp32)
    float p = sel ? __expf(sc) : 0.f;
    float s = p;
#pragma unroll
    for (int o = 16; o; o >>= 1) s += __shfl_xor_sync(0xffffffffu, s, o);
    float inv = 1.0f / s;
    float attn = p * inv;
    int pk = s_id | (r_id << 18);   // 18 bits | 9 bits

    unsigned mask = __ballot_sync(0xffffffffu, sel);
    float4 acc = make_float4(0.f, 0.f, 0.f, 0.f);
#pragma unroll
    for (int k = 0; k < TOPK; ++k) {
        int l = __ffs(mask) - 1;
        mask &= mask - 1;
        float wgt = __shfl_sync(0xffffffffu, attn, l);
        int pks = __shfl_sync(0xffffffffu, pk, l);
        int sk = pks & 0x3FFFF;
        int rk = pks >> 18;
        uint2 hn = *reinterpret_cast<const uint2*>(g_hnodeh + (size_t)sk * 64 + lane * 2);
        uint2 hr = *reinterpret_cast<const uint2*>(g_hrelh + rk * 64 + lane * 2);
        __half2 c0 = __hadd2(*reinterpret_cast<__half2*>(&hn.x), *reinterpret_cast<__half2*>(&hr.x));
        __half2 c1 = __hadd2(*reinterpret_cast<__half2*>(&hn.y), *reinterpret_cast<__half2*>(&hr.y));
        float2 f0 = __half22float2(c0);
        float2 f1 = __half22float2(c1);
        acc.x += wgt * f0.x;
        acc.y += wgt * f0.y;
        acc.z += wgt * f1.x;
        acc.w += wgt * f1.y;
    }
    *reinterpret_cast<float4*>(g_neigh + (size_t)n * HD + lane * 4) = acc;
}

// ---------------------------------------------------------------
extern "C" void kernel_launch(void* const* d_in, const int* in_sizes, int n_in,
                              void* d_out, int out_size) {
    const float* ent   = (const float*)d_in[0];
    const float* rel   = (const float*)d_in[1];
    const float* W     = (const float*)d_in[2];
    const float* Wr    = (const float*)d_in[3];
    const float* a     = (const float*)d_in[4];
    const float* nw    = (const float*)d_in[5];
    const int*   src   = (const int*)d_in[6];
    const int*   relid = (const int*)d_in[7];
    float* out = (float*)d_out;

    float *p_neigh, *p_ssrc, *p_sdst, *p_srel;
    unsigned char* p_img;
    cudaGetSymbolAddress((void**)&p_neigh, g_neigh);
    cudaGetSymbolAddress((void**)&p_ssrc, g_ssrc);
    cudaGetSymbolAddress((void**)&p_sdst, g_sdst);
    cudaGetSymbolAddress((void**)&p_srel, g_srel);
    cudaGetSymbolAddress((void**)&p_img, g_Bimg);

    const int SMEM = 131072;
    cudaFuncSetAttribute(gemm_hmma<1>, cudaFuncAttributeMaxDynamicSharedMemorySize, SMEM);
    cudaFuncSetAttribute(gemm_hmma<2>, cudaFuncAttributeMaxDynamicSharedMemorySize, SMEM);
    cudaFuncSetAttribute(gemm_hmma<3>, cudaFuncAttributeMaxDynamicSharedMemorySize, SMEM);

    prep_kernel<<<3, 256>>>(W, Wr, nw);

    const int NB = (NENT + 127) / 128;
    // h_node (fp16 image) + fused s_src/s_dst
    gemm_hmma<2><<<NB, 256, SMEM>>>(ent, p_img, nullptr, NENT, a, p_ssrc, p_sdst);
    // h_rel (fp16 image) + fused s_rel
    gemm_hmma<3><<<(NRELN + 127) / 128, 256, SMEM>>>(rel, p_img + 65536, nullptr, NRELN, a, p_srel, nullptr);
    // attention + aggregation (fp16 gathers)
    attn_kernel<<<(NENT * 32 + 255) / 256, 256>>>(src, relid);
    // out = tanh(neigh @ neigh_w)
    gemm_hmma<1><<<NB, 256, SMEM>>>(p_neigh, p_img + 2 * 65536, out, NENT, nullptr, nullptr, nullptr);
}

// round 8
// speedup vs baseline: 1.5669x; 1.2221x over previous
#include <cuda_runtime.h>
#include <cuda_fp16.h>
#include <math.h>
#include <stdint.h>

#define NENT 150000
#define NRELN 500
#define HD 128
#define DEG 32
#define TOPK 10

// -------- scratch (device globals; no allocation allowed) --------
__device__ uint32_t g_neighh[150016 * 64];  // neigh as half2 pairs
__device__ uint32_t g_hnodeh[150016 * 64];  // h_node as half2 pairs
__device__ uint32_t g_hrelh[512 * 64];      // h_rel  as half2 pairs
__device__ float g_ssrc[150016];
__device__ float g_sdst[150016];
__device__ float g_srel[512];
__device__ float g_wv[3][128];              // W@a1, W@a2, Wr@a3 (exact score vectors)
// pre-transposed + swizzled fp16-split weight images: [matrix][hi 32KB | lo 32KB]
__device__ __align__(16) unsigned char g_Bimg[3][65536];

// ================= helpers =================
__device__ __forceinline__ uint32_t smem_u32(const void* p) {
    uint32_t a;
    asm("{ .reg .u64 t; cvta.to.shared.u64 t, %1; cvt.u32.u64 %0, t; }" : "=r"(a) : "l"(p));
    return a;
}
__device__ __forceinline__ void ldsm_x4(uint32_t* r, uint32_t addr) {
    asm volatile("ldmatrix.sync.aligned.m8n8.x4.shared.b16 {%0,%1,%2,%3}, [%4];"
                 : "=r"(r[0]), "=r"(r[1]), "=r"(r[2]), "=r"(r[3]) : "r"(addr));
}
__device__ __forceinline__ void ldsm_x2(uint32_t* r, uint32_t addr) {
    asm volatile("ldmatrix.sync.aligned.m8n8.x2.shared.b16 {%0,%1}, [%2];"
                 : "=r"(r[0]), "=r"(r[1]) : "r"(addr));
}
__device__ __forceinline__ void mma_f16(float* d, const uint32_t* a, uint32_t b0, uint32_t b1) {
    asm volatile(
        "mma.sync.aligned.m16n8k16.row.col.f32.f16.f16.f32 "
        "{%0,%1,%2,%3}, {%4,%5,%6,%7}, {%8,%9}, {%0,%1,%2,%3};"
        : "+f"(d[0]), "+f"(d[1]), "+f"(d[2]), "+f"(d[3])
        : "r"(a[0]), "r"(a[1]), "r"(a[2]), "r"(a[3]), "r"(b0), "r"(b1));
}
__device__ __forceinline__ void h_split(float v, __half& h, __half& l) {
    h = __float2half_rn(v);
    l = __float2half_rn(v - __half2float(h));
}
__device__ __forceinline__ uint32_t pack2(__half a, __half b) {
    __half2 t;
    t.x = a; t.y = b;
    return *reinterpret_cast<uint32_t*>(&t);
}
// tile layout: row-major rows of 128 f16 (256B = 16 units of 16B), unit XOR-swizzled
__device__ __forceinline__ uint32_t img_off(int n, int k) {
    return (uint32_t)(n * 256 + ((((k >> 3) ^ (n & 7))) << 4) + (k & 7) * 2);
}

// ---------------------------------------------------------------
// prep: blockIdx 0..2 build weight images; blockIdx 3 computes the
// exact score vectors w1 = W@a1, w2 = W@a2, w3 = Wr@a3 (fp32).
// ---------------------------------------------------------------
__global__ void __launch_bounds__(256) prep_kernel(const float* __restrict__ W,
                                                   const float* __restrict__ Wr,
                                                   const float* __restrict__ Nw,
                                                   const float* __restrict__ a) {
    if (blockIdx.x == 3) {
        int k = threadIdx.x;   // 0..255: first 128 -> w1/w2, next 128 -> w3
        if (k < 128) {
            float d1 = 0.f, d2 = 0.f;
            for (int n = 0; n < 128; ++n) {
                float wv = W[k * 128 + n];
                d1 += wv * a[n];
                d2 += wv * a[128 + n];
            }
            g_wv[0][k] = d1;
            g_wv[1][k] = d2;
        } else {
            int kk = k - 128;
            float d3 = 0.f;
            for (int n = 0; n < 128; ++n) d3 += Wr[kk * 128 + n] * a[256 + n];
            g_wv[2][kk] = d3;
        }
        return;
    }
    const float* M = (blockIdx.x == 0) ? W : (blockIdx.x == 1) ? Wr : Nw;
    unsigned char* img = g_Bimg[blockIdx.x];
    for (int idx = threadIdx.x; idx < 128 * 128; idx += 256) {
        int k = idx >> 7, n = idx & 127;
        float v = M[idx];
        __half h, l;
        h_split(v, h, l);
        uint32_t off = img_off(n, k);
        *reinterpret_cast<__half*>(img + off) = h;
        *reinterpret_cast<__half*>(img + 32768 + off) = l;
    }
}

// ---------------------------------------------------------------
// HMMA GEMM: D = A[M,128] @ B (image).  2-pass: Ah*Bh + Ah*Bl.
// AHALF: A source is fp16 image (straight swizzled copy, exact).
// EPI: 1 = tanh -> C fp32;
//      2 = fp16 image to g_hnodeh; exact fp32 scores s1/s2 from A (w1,w2)
//      3 = fp16 image to g_hrelh;  exact fp32 score  s1    from A (w3)
// smem: A 32KB | BH 32KB | BL 32KB = 96KB -> 2 CTAs/SM.
// ---------------------------------------------------------------
template <int EPI, bool AHALF>
__global__ void __launch_bounds__(256) gemm_hmma(const void* __restrict__ Asrc,
                                                 const unsigned char* __restrict__ Bimg,
                                                 float* __restrict__ C, int M,
                                                 float* __restrict__ s1,
                                                 float* __restrict__ s2) {
    extern __shared__ __align__(16) unsigned char dynsm[];

    const int tid = threadIdx.x;
    const int wid = tid >> 5;
    const int lane = tid & 31;
    const int row0 = blockIdx.x * 128;

    // ---- B: straight 64KB copy of pre-swizzled hi|lo image ----
    {
        const uint4* srcB = reinterpret_cast<const uint4*>(Bimg);
        uint4* dstB = reinterpret_cast<uint4*>(dynsm + 32768);
#pragma unroll
        for (int i = 0; i < 16; ++i) dstB[tid + i * 256] = srcB[tid + i * 256];
    }
    // ---- A -> smem (32KB) (+ fused exact fp32 scores for EPI>=2) ----
    if (AHALF) {
        const uint4* srcA = reinterpret_cast<const uint4*>(Asrc) + (size_t)row0 * 16;
#pragma unroll
        for (int it = 0; it < 8; ++it) {
            int idx = tid + it * 256;
            int r = idx >> 4;
            int u = idx & 15;
            uint4 v = srcA[idx];
            *reinterpret_cast<uint4*>(dynsm + r * 256 + (((u ^ (r & 7))) << 4)) = v;
        }
    } else {
        const float* A = reinterpret_cast<const float*>(Asrc);
#pragma unroll
        for (int it = 0; it < 8; ++it) {
            int idx = tid + it * 256;
            int r = idx >> 4;
            int u = idx & 15;
            int gr = row0 + r;
            float4 v0 = make_float4(0.f, 0.f, 0.f, 0.f);
            float4 v1 = v0;
            if (gr < M) {
                v0 = *reinterpret_cast<const float4*>(A + (size_t)gr * HD + u * 8);
                v1 = *reinterpret_cast<const float4*>(A + (size_t)gr * HD + u * 8 + 4);
            }
            uint32_t off = r * 256 + (((u ^ (r & 7))) << 4);
            *reinterpret_cast<uint4*>(dynsm + off) = make_uint4(
                pack2(__float2half_rn(v0.x), __float2half_rn(v0.y)),
                pack2(__float2half_rn(v0.z), __float2half_rn(v0.w)),
                pack2(__float2half_rn(v1.x), __float2half_rn(v1.y)),
                pack2(__float2half_rn(v1.z), __float2half_rn(v1.w)));
            if (EPI >= 2) {
                const int wi = (EPI == 2) ? 0 : 2;
                float4 wa = *reinterpret_cast<const float4*>(&g_wv[wi][u * 8]);
                float4 wb = *reinterpret_cast<const float4*>(&g_wv[wi][u * 8 + 4]);
                float p1 = v0.x * wa.x + v0.y * wa.y + v0.z * wa.z + v0.w * wa.w +
                           v1.x * wb.x + v1.y * wb.y + v1.z * wb.z + v1.w * wb.w;
                float p2 = 0.f;
                if (EPI == 2) {
                    float4 wc = *reinterpret_cast<const float4*>(&g_wv[1][u * 8]);
                    float4 wd = *reinterpret_cast<const float4*>(&g_wv[1][u * 8 + 4]);
                    p2 = v0.x * wc.x + v0.y * wc.y + v0.z * wc.z + v0.w * wc.w +
                         v1.x * wd.x + v1.y * wd.y + v1.z * wd.z + v1.w * wd.w;
                }
#pragma unroll
                for (int o = 1; o < 16; o <<= 1) {
                    p1 += __shfl_xor_sync(0xffffffffu, p1, o);
                    if (EPI == 2) p2 += __shfl_xor_sync(0xffffffffu, p2, o);
                }
                if ((tid & 15) == 0 && gr < M) {
                    s1[gr] = p1;
                    if (EPI == 2) s2[gr] = p2;
                }
            }
        }
    }
    __syncthreads();

    // ---- compute ----
    const uint32_t sb = smem_u32(dynsm);
    const uint32_t AH = sb, BH = sb + 32768, BL = sb + 65536;
    const int wr = wid >> 1;
    const int wc = wid & 1;
    const int r0w = wr * 32;
    const int c0w = wc * 64;

    const int rA = lane & 15;
    const int uA = lane >> 4;
    const int axr = rA & 7;
    const int nB = lane & 7;
    const int uB = (lane >> 3) & 1;

    uint32_t arow[2], brow[8];
#pragma unroll
    for (int rb = 0; rb < 2; ++rb) arow[rb] = (uint32_t)(r0w + rb * 16 + rA) * 256;
#pragma unroll
    for (int nb = 0; nb < 8; ++nb) brow[nb] = (uint32_t)(c0w + nb * 8 + nB) * 256;

    float acc[2][8][4];
#pragma unroll
    for (int rb = 0; rb < 2; ++rb)
#pragma unroll
        for (int nb = 0; nb < 8; ++nb) {
            acc[rb][nb][0] = 0.f; acc[rb][nb][1] = 0.f;
            acc[rb][nb][2] = 0.f; acc[rb][nb][3] = 0.f;
        }

#pragma unroll
    for (int kb = 0; kb < 8; ++kb) {
        uint32_t offA = (uint32_t)((2 * kb + uA) ^ axr) << 4;
        uint32_t offB = (uint32_t)((2 * kb + uB) ^ nB) << 4;
        uint32_t ah[2][4];
        ldsm_x4(ah[0], AH + arow[0] + offA);
        ldsm_x4(ah[1], AH + arow[1] + offA);
#pragma unroll
        for (int nb = 0; nb < 8; ++nb) {
            uint32_t bh[2], bl[2];
            ldsm_x2(bh, BH + brow[nb] + offB);
            ldsm_x2(bl, BL + brow[nb] + offB);
#pragma unroll
            for (int rb = 0; rb < 2; ++rb) {
                mma_f16(acc[rb][nb], ah[rb], bh[0], bh[1]);
                mma_f16(acc[rb][nb], ah[rb], bl[0], bl[1]);
            }
        }
    }

    // ---- epilogue ----
    const int tg = lane >> 2, tig = lane & 3;

#pragma unroll
    for (int rb = 0; rb < 2; ++rb)
#pragma unroll
        for (int nb = 0; nb < 8; ++nb) {
            float* d = acc[rb][nb];
            int c = c0w + nb * 8 + tig * 2;
            int r1 = row0 + r0w + rb * 16 + tg;
            if (EPI == 1) {
                float2 lo = make_float2(tanhf(d[0]), tanhf(d[1]));
                float2 hi = make_float2(tanhf(d[2]), tanhf(d[3]));
                if (r1 < M)
                    *reinterpret_cast<float2*>(C + (size_t)r1 * HD + c) = lo;
                if (r1 + 8 < M)
                    *reinterpret_cast<float2*>(C + (size_t)(r1 + 8) * HD + c) = hi;
            }
            if (EPI == 2) {
                if (r1 < M)
                    g_hnodeh[(size_t)r1 * 64 + (c >> 1)] = pack2(__float2half_rn(d[0]), __float2half_rn(d[1]));
                if (r1 + 8 < M)
                    g_hnodeh[(size_t)(r1 + 8) * 64 + (c >> 1)] = pack2(__float2half_rn(d[2]), __float2half_rn(d[3]));
            }
            if (EPI == 3) {
                if (r1 < M)
                    g_hrelh[r1 * 64 + (c >> 1)] = pack2(__float2half_rn(d[0]), __float2half_rn(d[1]));
                if (r1 + 8 < M)
                    g_hrelh[(r1 + 8) * 64 + (c >> 1)] = pack2(__float2half_rn(d[2]), __float2half_rn(d[3]));
            }
        }
}

// ---------------------------------------------------------------
// Attention: warp per node; fp16 gathers; rank-based top-k;
// no-max softmax; packed (src|rel) shuffles; fp16 neigh output.
// ---------------------------------------------------------------
__global__ void __launch_bounds__(256) attn_kernel(const int* __restrict__ src,
                                                   const int* __restrict__ relid) {
    __shared__ float ssc[8][32];
    int warp = (blockIdx.x * blockDim.x + threadIdx.x) >> 5;
    int w = threadIdx.x >> 5;
    int lane = threadIdx.x & 31;
    if (warp >= NENT) return;
    const int n = warp;

    int s_id = src[(size_t)n * DEG + lane];
    int r_id = relid[(size_t)n * DEG + lane];
    float sc = g_ssrc[s_id] + g_sdst[n] + g_srel[r_id];
    sc = sc > 0.f ? sc : 0.2f * sc;  // leaky_relu 0.2

    ssc[w][lane] = sc;
    __syncwarp();
    int rank = 0;
#pragma unroll
    for (int j = 0; j < 32; ++j) {
        float o = ssc[w][j];
        rank += (o > sc) || (o == sc && j < lane);
    }
    bool sel = rank < TOPK;

    float p = sel ? __expf(sc) : 0.f;
    float s = p;
#pragma unroll
    for (int o = 16; o; o >>= 1) s += __shfl_xor_sync(0xffffffffu, s, o);
    float attn = p / s;
    int pk = s_id | (r_id << 18);

    unsigned mask = __ballot_sync(0xffffffffu, sel);
    float4 acc = make_float4(0.f, 0.f, 0.f, 0.f);
#pragma unroll
    for (int k = 0; k < TOPK; ++k) {
        int l = __ffs(mask) - 1;
        mask &= mask - 1;
        float wgt = __shfl_sync(0xffffffffu, attn, l);
        int pks = __shfl_sync(0xffffffffu, pk, l);
        int sk = pks & 0x3FFFF;
        int rk = pks >> 18;
        uint2 hn = *reinterpret_cast<const uint2*>(g_hnodeh + (size_t)sk * 64 + lane * 2);
        uint2 hr = *reinterpret_cast<const uint2*>(g_hrelh + rk * 64 + lane * 2);
        __half2 c0 = __hadd2(*reinterpret_cast<__half2*>(&hn.x), *reinterpret_cast<__half2*>(&hr.x));
        __half2 c1 = __hadd2(*reinterpret_cast<__half2*>(&hn.y), *reinterpret_cast<__half2*>(&hr.y));
        float2 f0 = __half22float2(c0);
        float2 f1 = __half22float2(c1);
        acc.x += wgt * f0.x;
        acc.y += wgt * f0.y;
        acc.z += wgt * f1.x;
        acc.w += wgt * f1.y;
    }
    *reinterpret_cast<uint2*>(g_neighh + (size_t)n * 64 + lane * 2) =
        make_uint2(pack2(__float2half_rn(acc.x), __float2half_rn(acc.y)),
                   pack2(__float2half_rn(acc.z), __float2half_rn(acc.w)));
}

// ---------------------------------------------------------------
extern "C" void kernel_launch(void* const* d_in, const int* in_sizes, int n_in,
                              void* d_out, int out_size) {
    const float* ent   = (const float*)d_in[0];
    const float* rel   = (const float*)d_in[1];
    const float* W     = (const float*)d_in[2];
    const float* Wr    = (const float*)d_in[3];
    const float* a     = (const float*)d_in[4];
    const float* nw    = (const float*)d_in[5];
    const int*   src   = (const int*)d_in[6];
    const int*   relid = (const int*)d_in[7];
    float* out = (float*)d_out;

    float *p_ssrc, *p_sdst, *p_srel;
    uint32_t* p_neighh;
    unsigned char* p_img;
    cudaGetSymbolAddress((void**)&p_neighh, g_neighh);
    cudaGetSymbolAddress((void**)&p_ssrc, g_ssrc);
    cudaGetSymbolAddress((void**)&p_sdst, g_sdst);
    cudaGetSymbolAddress((void**)&p_srel, g_srel);
    cudaGetSymbolAddress((void**)&p_img, g_Bimg);

    const int SMEM = 98304;
    cudaFuncSetAttribute((const void*)gemm_hmma<1, true>,  cudaFuncAttributeMaxDynamicSharedMemorySize, SMEM);
    cudaFuncSetAttribute((const void*)gemm_hmma<2, false>, cudaFuncAttributeMaxDynamicSharedMemorySize, SMEM);
    cudaFuncSetAttribute((const void*)gemm_hmma<3, false>, cudaFuncAttributeMaxDynamicSharedMemorySize, SMEM);

    prep_kernel<<<4, 256>>>(W, Wr, nw, a);

    const int NB = (NENT + 127) / 128;
    // h_node (fp16 image) + exact fp32 s_src/s_dst from A
    gemm_hmma<2, false><<<NB, 256, SMEM>>>(ent, p_img, nullptr, NENT, p_ssrc, p_sdst);
    // h_rel (fp16 image) + exact fp32 s_rel from A
    gemm_hmma<3, false><<<(NRELN + 127) / 128, 256, SMEM>>>(rel, p_img + 65536, nullptr, NRELN, p_srel, nullptr);
    // attention + aggregation (fp16 gathers, fp16 neigh out)
    attn_kernel<<<(NENT * 32 + 255) / 256, 256>>>(src, relid);
    // out = tanh(neigh @ neigh_w)   (A exact fp16, full B split)
    gemm_hmma<1, true><<<NB, 256, SMEM>>>(p_neighh, p_img + 2 * 65536, out, NENT, nullptr, nullptr);
}

// round 9
// speedup vs baseline: 1.6216x; 1.0349x over previous
#include <cuda_runtime.h>
#include <cuda_fp16.h>
#include <math.h>
#include <stdint.h>

#define NENT 150000
#define NRELN 500
#define HD 128
#define DEG 32
#define TOPK 10

// -------- scratch (device globals; no allocation allowed) --------
__device__ uint32_t g_neighh[150016 * 64];  // neigh as half2 pairs
__device__ uint32_t g_hnodeh[150016 * 64];  // h_node as half2 pairs
__device__ uint32_t g_hrelh[512 * 64];      // h_rel  as half2 pairs
__device__ float g_ssrc[150016];
__device__ float g_sdst[150016];
__device__ float g_srel[512];
__device__ float g_wv[3][128];              // W@a1, W@a2, Wr@a3 (exact score vectors)
// pre-transposed + swizzled fp16-split weight images: [matrix][hi 32KB | lo 32KB]
__device__ __align__(16) unsigned char g_Bimg[3][65536];

// ================= helpers =================
__device__ __forceinline__ uint32_t smem_u32(const void* p) {
    uint32_t a;
    asm("{ .reg .u64 t; cvta.to.shared.u64 t, %1; cvt.u32.u64 %0, t; }" : "=r"(a) : "l"(p));
    return a;
}
__device__ __forceinline__ void ldsm_x4(uint32_t* r, uint32_t addr) {
    asm volatile("ldmatrix.sync.aligned.m8n8.x4.shared.b16 {%0,%1,%2,%3}, [%4];"
                 : "=r"(r[0]), "=r"(r[1]), "=r"(r[2]), "=r"(r[3]) : "r"(addr));
}
__device__ __forceinline__ void ldsm_x2(uint32_t* r, uint32_t addr) {
    asm volatile("ldmatrix.sync.aligned.m8n8.x2.shared.b16 {%0,%1}, [%2];"
                 : "=r"(r[0]), "=r"(r[1]) : "r"(addr));
}
__device__ __forceinline__ void mma_f16(float* d, const uint32_t* a, uint32_t b0, uint32_t b1) {
    asm volatile(
        "mma.sync.aligned.m16n8k16.row.col.f32.f16.f16.f32 "
        "{%0,%1,%2,%3}, {%4,%5,%6,%7}, {%8,%9}, {%0,%1,%2,%3};"
        : "+f"(d[0]), "+f"(d[1]), "+f"(d[2]), "+f"(d[3])
        : "r"(a[0]), "r"(a[1]), "r"(a[2]), "r"(a[3]), "r"(b0), "r"(b1));
}
__device__ __forceinline__ void h_split(float v, __half& h, __half& l) {
    h = __float2half_rn(v);
    l = __float2half_rn(v - __half2float(h));
}
__device__ __forceinline__ uint32_t pack2(__half a, __half b) {
    __half2 t;
    t.x = a; t.y = b;
    return *reinterpret_cast<uint32_t*>(&t);
}
__device__ __forceinline__ __half2 u2h2(uint32_t u) {
    return *reinterpret_cast<__half2*>(&u);
}
// tile layout: row-major rows of 128 f16 (256B = 16 units of 16B), unit XOR-swizzled
__device__ __forceinline__ uint32_t img_off(int n, int k) {
    return (uint32_t)(n * 256 + ((((k >> 3) ^ (n & 7))) << 4) + (k & 7) * 2);
}

// ---------------------------------------------------------------
// prep: blockIdx 0..2 build weight images; blockIdx 3 computes the
// exact score vectors w1 = W@a1, w2 = W@a2, w3 = Wr@a3 (fp32).
// ---------------------------------------------------------------
__global__ void __launch_bounds__(256) prep_kernel(const float* __restrict__ W,
                                                   const float* __restrict__ Wr,
                                                   const float* __restrict__ Nw,
                                                   const float* __restrict__ a) {
    if (blockIdx.x == 3) {
        int k = threadIdx.x;   // 0..255: first 128 -> w1/w2, next 128 -> w3
        if (k < 128) {
            float d1 = 0.f, d2 = 0.f;
            for (int n = 0; n < 128; ++n) {
                float wv = W[k * 128 + n];
                d1 += wv * a[n];
                d2 += wv * a[128 + n];
            }
            g_wv[0][k] = d1;
            g_wv[1][k] = d2;
        } else {
            int kk = k - 128;
            float d3 = 0.f;
            for (int n = 0; n < 128; ++n) d3 += Wr[kk * 128 + n] * a[256 + n];
            g_wv[2][kk] = d3;
        }
        return;
    }
    const float* M = (blockIdx.x == 0) ? W : (blockIdx.x == 1) ? Wr : Nw;
    unsigned char* img = g_Bimg[blockIdx.x];
    for (int idx = threadIdx.x; idx < 128 * 128; idx += 256) {
        int k = idx >> 7, n = idx & 127;
        float v = M[idx];
        __half h, l;
        h_split(v, h, l);
        uint32_t off = img_off(n, k);
        *reinterpret_cast<__half*>(img + off) = h;
        *reinterpret_cast<__half*>(img + 32768 + off) = l;
    }
}

// ---------------------------------------------------------------
// HMMA GEMM: D = A[M,128] @ B (image).  2-pass: Ah*Bh + Ah*Bl.
// AHALF: A source is fp16 image (straight swizzled copy, exact).
// EPI: 1 = tanh -> C fp32;
//      2 = fp16 image to g_hnodeh; exact fp32 scores s1/s2 from A (w1,w2)
//      3 = fp16 image to g_hrelh;  exact fp32 score  s1    from A (w3)
// smem: A 32KB | BH 32KB | BL 32KB = 96KB -> 2 CTAs/SM.
// ---------------------------------------------------------------
template <int EPI, bool AHALF>
__global__ void __launch_bounds__(256) gemm_hmma(const void* __restrict__ Asrc,
                                                 const unsigned char* __restrict__ Bimg,
                                                 float* __restrict__ C, int M,
                                                 float* __restrict__ s1,
                                                 float* __restrict__ s2) {
    extern __shared__ __align__(16) unsigned char dynsm[];

    const int tid = threadIdx.x;
    const int wid = tid >> 5;
    const int lane = tid & 31;
    const int row0 = blockIdx.x * 128;

    // ---- B: straight 64KB copy of pre-swizzled hi|lo image ----
    {
        const uint4* srcB = reinterpret_cast<const uint4*>(Bimg);
        uint4* dstB = reinterpret_cast<uint4*>(dynsm + 32768);
#pragma unroll
        for (int i = 0; i < 16; ++i) dstB[tid + i * 256] = srcB[tid + i * 256];
    }
    // ---- A -> smem (32KB) (+ fused exact fp32 scores for EPI>=2) ----
    if (AHALF) {
        const uint4* srcA = reinterpret_cast<const uint4*>(Asrc) + (size_t)row0 * 16;
#pragma unroll
        for (int it = 0; it < 8; ++it) {
            int idx = tid + it * 256;
            int r = idx >> 4;
            int u = idx & 15;
            uint4 v = srcA[idx];
            *reinterpret_cast<uint4*>(dynsm + r * 256 + (((u ^ (r & 7))) << 4)) = v;
        }
    } else {
        const float* A = reinterpret_cast<const float*>(Asrc);
#pragma unroll
        for (int it = 0; it < 8; ++it) {
            int idx = tid + it * 256;
            int r = idx >> 4;
            int u = idx & 15;
            int gr = row0 + r;
            float4 v0 = make_float4(0.f, 0.f, 0.f, 0.f);
            float4 v1 = v0;
            if (gr < M) {
                v0 = *reinterpret_cast<const float4*>(A + (size_t)gr * HD + u * 8);
                v1 = *reinterpret_cast<const float4*>(A + (size_t)gr * HD + u * 8 + 4);
            }
            uint32_t off = r * 256 + (((u ^ (r & 7))) << 4);
            *reinterpret_cast<uint4*>(dynsm + off) = make_uint4(
                pack2(__float2half_rn(v0.x), __float2half_rn(v0.y)),
                pack2(__float2half_rn(v0.z), __float2half_rn(v0.w)),
                pack2(__float2half_rn(v1.x), __float2half_rn(v1.y)),
                pack2(__float2half_rn(v1.z), __float2half_rn(v1.w)));
            if (EPI >= 2) {
                const int wi = (EPI == 2) ? 0 : 2;
                float4 wa = *reinterpret_cast<const float4*>(&g_wv[wi][u * 8]);
                float4 wb = *reinterpret_cast<const float4*>(&g_wv[wi][u * 8 + 4]);
                float p1 = v0.x * wa.x + v0.y * wa.y + v0.z * wa.z + v0.w * wa.w +
                           v1.x * wb.x + v1.y * wb.y + v1.z * wb.z + v1.w * wb.w;
                float p2 = 0.f;
                if (EPI == 2) {
                    float4 wc = *reinterpret_cast<const float4*>(&g_wv[1][u * 8]);
                    float4 wd = *reinterpret_cast<const float4*>(&g_wv[1][u * 8 + 4]);
                    p2 = v0.x * wc.x + v0.y * wc.y + v0.z * wc.z + v0.w * wc.w +
                         v1.x * wd.x + v1.y * wd.y + v1.z * wd.z + v1.w * wd.w;
                }
#pragma unroll
                for (int o = 1; o < 16; o <<= 1) {
                    p1 += __shfl_xor_sync(0xffffffffu, p1, o);
                    if (EPI == 2) p2 += __shfl_xor_sync(0xffffffffu, p2, o);
                }
                if ((tid & 15) == 0 && gr < M) {
                    s1[gr] = p1;
                    if (EPI == 2) s2[gr] = p2;
                }
            }
        }
    }
    __syncthreads();

    // ---- compute ----
    const uint32_t sb = smem_u32(dynsm);
    const uint32_t AH = sb, BH = sb + 32768, BL = sb + 65536;
    const int wr = wid >> 1;
    const int wc = wid & 1;
    const int r0w = wr * 32;
    const int c0w = wc * 64;

    const int rA = lane & 15;
    const int uA = lane >> 4;
    const int axr = rA & 7;
    const int nB = lane & 7;
    const int uB = (lane >> 3) & 1;

    uint32_t arow[2], brow[8];
#pragma unroll
    for (int rb = 0; rb < 2; ++rb) arow[rb] = (uint32_t)(r0w + rb * 16 + rA) * 256;
#pragma unroll
    for (int nb = 0; nb < 8; ++nb) brow[nb] = (uint32_t)(c0w + nb * 8 + nB) * 256;

    float acc[2][8][4];
#pragma unroll
    for (int rb = 0; rb < 2; ++rb)
#pragma unroll
        for (int nb = 0; nb < 8; ++nb) {
            acc[rb][nb][0] = 0.f; acc[rb][nb][1] = 0.f;
            acc[rb][nb][2] = 0.f; acc[rb][nb][3] = 0.f;
        }

#pragma unroll
    for (int kb = 0; kb < 8; ++kb) {
        uint32_t offA = (uint32_t)((2 * kb + uA) ^ axr) << 4;
        uint32_t offB = (uint32_t)((2 * kb + uB) ^ nB) << 4;
        uint32_t ah[2][4];
        ldsm_x4(ah[0], AH + arow[0] + offA);
        ldsm_x4(ah[1], AH + arow[1] + offA);
#pragma unroll
        for (int nb = 0; nb < 8; ++nb) {
            uint32_t bh[2], bl[2];
            ldsm_x2(bh, BH + brow[nb] + offB);
            ldsm_x2(bl, BL + brow[nb] + offB);
#pragma unroll
            for (int rb = 0; rb < 2; ++rb) {
                mma_f16(acc[rb][nb], ah[rb], bh[0], bh[1]);
                mma_f16(acc[rb][nb], ah[rb], bl[0], bl[1]);
            }
        }
    }

    // ---- epilogue ----
    const int tg = lane >> 2, tig = lane & 3;

#pragma unroll
    for (int rb = 0; rb < 2; ++rb)
#pragma unroll
        for (int nb = 0; nb < 8; ++nb) {
            float* d = acc[rb][nb];
            int c = c0w + nb * 8 + tig * 2;
            int r1 = row0 + r0w + rb * 16 + tg;
            if (EPI == 1) {
                float2 lo = make_float2(tanhf(d[0]), tanhf(d[1]));
                float2 hi = make_float2(tanhf(d[2]), tanhf(d[3]));
                if (r1 < M)
                    *reinterpret_cast<float2*>(C + (size_t)r1 * HD + c) = lo;
                if (r1 + 8 < M)
                    *reinterpret_cast<float2*>(C + (size_t)(r1 + 8) * HD + c) = hi;
            }
            if (EPI == 2) {
                if (r1 < M)
                    g_hnodeh[(size_t)r1 * 64 + (c >> 1)] = pack2(__float2half_rn(d[0]), __float2half_rn(d[1]));
                if (r1 + 8 < M)
                    g_hnodeh[(size_t)(r1 + 8) * 64 + (c >> 1)] = pack2(__float2half_rn(d[2]), __float2half_rn(d[3]));
            }
            if (EPI == 3) {
                if (r1 < M)
                    g_hrelh[r1 * 64 + (c >> 1)] = pack2(__float2half_rn(d[0]), __float2half_rn(d[1]));
                if (r1 + 8 < M)
                    g_hrelh[(r1 + 8) * 64 + (c >> 1)] = pack2(__float2half_rn(d[2]), __float2half_rn(d[3]));
            }
        }
}

// ---------------------------------------------------------------
// Attention: warp per node; rank-based top-k; rank doubles as the
// compaction slot (selected ranks are exactly 0..9). Gather with
// 16 lanes per neighbor, 2 neighbors per iteration via LDG.128.
// ---------------------------------------------------------------
__global__ void __launch_bounds__(256) attn_kernel(const int* __restrict__ src,
                                                   const int* __restrict__ relid) {
    __shared__ __align__(16) float ssc[8][32];
    __shared__ float swgt[8][16];
    __shared__ int spk[8][16];

    int warp = (blockIdx.x * blockDim.x + threadIdx.x) >> 5;
    int w = threadIdx.x >> 5;
    int lane = threadIdx.x & 31;
    if (warp >= NENT) return;
    const int n = warp;

    int s_id = src[(size_t)n * DEG + lane];
    int r_id = relid[(size_t)n * DEG + lane];
    float sc = g_ssrc[s_id] + g_sdst[n] + g_srel[r_id];
    sc = sc > 0.f ? sc : 0.2f * sc;  // leaky_relu 0.2

    ssc[w][lane] = sc;
    __syncwarp();
    int rank = 0;
#pragma unroll
    for (int j4 = 0; j4 < 8; ++j4) {
        float4 q = *reinterpret_cast<const float4*>(&ssc[w][j4 * 4]);
        int j = j4 * 4;
        rank += (q.x > sc) || (q.x == sc && (j + 0) < lane);
        rank += (q.y > sc) || (q.y == sc && (j + 1) < lane);
        rank += (q.z > sc) || (q.z == sc && (j + 2) < lane);
        rank += (q.w > sc) || (q.w == sc && (j + 3) < lane);
    }
    bool sel = rank < TOPK;

    // softmax over selected, no max shift (|sc| small; exp safe in fp32)
    float p = sel ? __expf(sc) : 0.f;
    float s = p;
#pragma unroll
    for (int o = 16; o; o >>= 1) s += __shfl_xor_sync(0xffffffffu, s, o);

    // rank IS the compaction slot: selected lanes have distinct ranks 0..9
    if (sel) {
        swgt[w][rank] = p / s;
        spk[w][rank] = s_id | (r_id << 18);   // 18 bits | 9 bits
    }
    __syncwarp();

    // gather: lanes 0-15 handle even neighbors, 16-31 odd; 16B per lane per row
    const int half = lane >> 4;
    const int j = lane & 15;
    float acc[8];
#pragma unroll
    for (int d = 0; d < 8; ++d) acc[d] = 0.f;

#pragma unroll
    for (int it = 0; it < 5; ++it) {
        int k = it * 2 + half;
        float wgt = swgt[w][k];
        int pks = spk[w][k];
        int sk = pks & 0x3FFFF;
        int rk = pks >> 18;
        uint4 hn = *reinterpret_cast<const uint4*>(g_hnodeh + (size_t)sk * 64 + j * 4);
        uint4 hr = *reinterpret_cast<const uint4*>(g_hrelh + rk * 64 + j * 4);
        float2 f0 = __half22float2(__hadd2(u2h2(hn.x), u2h2(hr.x)));
        float2 f1 = __half22float2(__hadd2(u2h2(hn.y), u2h2(hr.y)));
        float2 f2 = __half22float2(__hadd2(u2h2(hn.z), u2h2(hr.z)));
        float2 f3 = __half22float2(__hadd2(u2h2(hn.w), u2h2(hr.w)));
        acc[0] += wgt * f0.x; acc[1] += wgt * f0.y;
        acc[2] += wgt * f1.x; acc[3] += wgt * f1.y;
        acc[4] += wgt * f2.x; acc[5] += wgt * f2.y;
        acc[6] += wgt * f3.x; acc[7] += wgt * f3.y;
    }

    // combine even/odd halves: lane j += lane j+16
#pragma unroll
    for (int d = 0; d < 8; ++d) acc[d] += __shfl_down_sync(0xffffffffu, acc[d], 16);

    if (lane < 16) {
        uint4 o;
        o.x = pack2(__float2half_rn(acc[0]), __float2half_rn(acc[1]));
        o.y = pack2(__float2half_rn(acc[2]), __float2half_rn(acc[3]));
        o.z = pack2(__float2half_rn(acc[4]), __float2half_rn(acc[5]));
        o.w = pack2(__float2half_rn(acc[6]), __float2half_rn(acc[7]));
        *reinterpret_cast<uint4*>(g_neighh + (size_t)n * 64 + j * 4) = o;
    }
}

// ---------------------------------------------------------------
extern "C" void kernel_launch(void* const* d_in, const int* in_sizes, int n_in,
                              void* d_out, int out_size) {
    const float* ent   = (const float*)d_in[0];
    const float* rel   = (const float*)d_in[1];
    const float* W     = (const float*)d_in[2];
    const float* Wr    = (const float*)d_in[3];
    const float* a     = (const float*)d_in[4];
    const float* nw    = (const float*)d_in[5];
    const int*   src   = (const int*)d_in[6];
    const int*   relid = (const int*)d_in[7];
    float* out = (float*)d_out;

    float *p_ssrc, *p_sdst, *p_srel;
    uint32_t* p_neighh;
    unsigned char* p_img;
    cudaGetSymbolAddress((void**)&p_neighh, g_neighh);
    cudaGetSymbolAddress((void**)&p_ssrc, g_ssrc);
    cudaGetSymbolAddress((void**)&p_sdst, g_sdst);
    cudaGetSymbolAddress((void**)&p_srel, g_srel);
    cudaGetSymbolAddress((void**)&p_img, g_Bimg);

    const int SMEM = 98304;
    cudaFuncSetAttribute((const void*)gemm_hmma<1, true>,  cudaFuncAttributeMaxDynamicSharedMemorySize, SMEM);
    cudaFuncSetAttribute((const void*)gemm_hmma<2, false>, cudaFuncAttributeMaxDynamicSharedMemorySize, SMEM);
    cudaFuncSetAttribute((const void*)gemm_hmma<3, false>, cudaFuncAttributeMaxDynamicSharedMemorySize, SMEM);

    prep_kernel<<<4, 256>>>(W, Wr, nw, a);

    const int NB = (NENT + 127) / 128;
    // h_node (fp16 image) + exact fp32 s_src/s_dst from A
    gemm_hmma<2, false><<<NB, 256, SMEM>>>(ent, p_img, nullptr, NENT, p_ssrc, p_sdst);
    // h_rel (fp16 image) + exact fp32 s_rel from A
    gemm_hmma<3, false><<<(NRELN + 127) / 128, 256, SMEM>>>(rel, p_img + 65536, nullptr, NRELN, p_srel, nullptr);
    // attention + aggregation (fp16 gathers, fp16 neigh out)
    attn_kernel<<<(NENT * 32 + 255) / 256, 256>>>(src, relid);
    // out = tanh(neigh @ neigh_w)   (A exact fp16, full B split)
    gemm_hmma<1, true><<<NB, 256, SMEM>>>(p_neighh, p_img + 2 * 65536, out, NENT, nullptr, nullptr);
}